// round 1
// baseline (speedup 1.0000x reference)
#include <cuda_runtime.h>

#define N_E   8192
#define E_DIM 512
#define B_SZ  8
#define T_SZ  1024
#define ROWS  (B_SZ * T_SZ)          // 8192 zf rows
#define CT    (E_DIM * T_SZ)         // 524288, stride per batch in z / z_q
#define ZQ_ELEMS (B_SZ * E_DIM * T_SZ)  // 4194304

#define BM 64
#define BN 128
#define BK 16

// -------- scratch (no allocations allowed) --------
__device__ float g_codebook[N_E * E_DIM];     // 16 MB
__device__ float g_cbnorm[N_E];
__device__ unsigned long long g_best[ROWS];   // packed (orderable(score)<<32 | idx)
__device__ float g_partial[ROWS / 32];        // 256 loss partials
__device__ int g_lo[B_SZ], g_hi[B_SZ];

__device__ __forceinline__ unsigned int fkey(float f) {
    unsigned int u = __float_as_uint(f);
    return (u & 0x80000000u) ? ~u : (u | 0x80000000u);  // monotonic float->uint
}

// -------- K0: parse audio_domain (handles int32 or int64 storage) --------
__global__ void k_ranges(const int* __restrict__ ad) {
    if (threadIdx.x == 0) {
        // int64 little-endian with values 0..3 => odd 32-bit words all zero
        bool is64 = ((ad[1] | ad[3] | ad[5] | ad[7]) == 0);
        for (int b = 0; b < B_SZ; b++) {
            int dom = is64 ? ad[2 * b] : ad[b];
            int lo, hi;
            if (dom == 0)      { lo = 0;    hi = 2048; }
            else if (dom == 1) { lo = 2048; hi = 4096; }
            else if (dom == 2) { lo = 4096; hi = 8192; }
            else               { lo = 0;    hi = 8192; }
            g_lo[b] = lo; g_hi[b] = hi;
        }
    }
}

// -------- K0b: reset per-row argmin state --------
__global__ void k_init() {
    int i = blockIdx.x * blockDim.x + threadIdx.x;
    if (i < ROWS) g_best[i] = 0xFFFFFFFFFFFFFFFFull;
}

// -------- K1: codebook = emb(8192x512) @ proj_w(512x512)^T + b  --------
__global__ __launch_bounds__(256) void k_codebook(const float* __restrict__ E,
                                                  const float* __restrict__ W,
                                                  const float* __restrict__ bias) {
    __shared__ float As[BK][BM];   // [k][m]
    __shared__ float Bs[BK][BN];   // [k][n]
    const int tid = threadIdx.x;
    const int tx = tid & 15, ty = tid >> 4;
    const int m0 = blockIdx.x * BM;   // codebook row tile
    const int n0 = blockIdx.y * BN;   // dim tile

    const int la_m = tid >> 2;
    const int la_k = (tid & 3) * 4;
    const int lb_r = tid >> 2;
    const int lb_k = (tid & 3) * 4;

    float acc[4][8];
#pragma unroll
    for (int i = 0; i < 4; i++)
#pragma unroll
        for (int j = 0; j < 8; j++) acc[i][j] = 0.f;

    for (int k0 = 0; k0 < E_DIM; k0 += BK) {
        float4 av  = *(const float4*)(E + (size_t)(m0 + la_m) * E_DIM + k0 + la_k);
        float4 bv0 = *(const float4*)(W + (size_t)(n0 + lb_r) * E_DIM + k0 + lb_k);
        float4 bv1 = *(const float4*)(W + (size_t)(n0 + lb_r + 64) * E_DIM + k0 + lb_k);
        __syncthreads();
        As[la_k + 0][la_m] = av.x; As[la_k + 1][la_m] = av.y;
        As[la_k + 2][la_m] = av.z; As[la_k + 3][la_m] = av.w;
        Bs[lb_k + 0][lb_r] = bv0.x; Bs[lb_k + 1][lb_r] = bv0.y;
        Bs[lb_k + 2][lb_r] = bv0.z; Bs[lb_k + 3][lb_r] = bv0.w;
        Bs[lb_k + 0][lb_r + 64] = bv1.x; Bs[lb_k + 1][lb_r + 64] = bv1.y;
        Bs[lb_k + 2][lb_r + 64] = bv1.z; Bs[lb_k + 3][lb_r + 64] = bv1.w;
        __syncthreads();
#pragma unroll
        for (int k = 0; k < BK; k++) {
            float a[4], bb[8];
            *(float4*)a        = *(const float4*)&As[k][ty * 4];
            *(float4*)bb       = *(const float4*)&Bs[k][tx * 8];
            *(float4*)(bb + 4) = *(const float4*)&Bs[k][tx * 8 + 4];
#pragma unroll
            for (int i = 0; i < 4; i++)
#pragma unroll
                for (int j = 0; j < 8; j++) acc[i][j] += a[i] * bb[j];
        }
    }
#pragma unroll
    for (int i = 0; i < 4; i++) {
        int row = m0 + ty * 4 + i;
        float* cp = g_codebook + (size_t)row * E_DIM + n0 + tx * 8;
        float v[8];
#pragma unroll
        for (int j = 0; j < 8; j++) v[j] = acc[i][j] + __ldg(&bias[n0 + tx * 8 + j]);
        *(float4*)cp       = *(float4*)v;
        *(float4*)(cp + 4) = *(float4*)(v + 4);
    }
}

// -------- K2: cbnorm[n] = ||codebook[n]||^2 --------
__global__ void k_cbnorm() {
    int row  = blockIdx.x * 8 + (threadIdx.x >> 5);
    int lane = threadIdx.x & 31;
    const float4* p = (const float4*)(g_codebook + (size_t)row * E_DIM);
    float s = 0.f;
#pragma unroll
    for (int i = lane; i < E_DIM / 4; i += 32) {
        float4 v = p[i];
        s += v.x * v.x + v.y * v.y + v.z * v.z + v.w * v.w;
    }
#pragma unroll
    for (int o = 16; o; o >>= 1) s += __shfl_down_sync(0xffffffffu, s, o);
    if (lane == 0) g_cbnorm[row] = s;
}

// -------- K3: fused distance GEMM + masked argmin --------
// gridDim.x = 128 row-tiles (64 t each, single batch), gridDim.y = 4 n-chunks of 2048
__global__ __launch_bounds__(256) void k_argmin(const float* __restrict__ z) {
    const int bx = blockIdx.x;
    const int b  = bx >> 4;
    const int t0 = (bx & 15) * BM;
    const int c0 = blockIdx.y * 2048;
    const int lo = g_lo[b], hi = g_hi[b];
    if (c0 >= hi || c0 + 2048 <= lo) return;   // chunks align with domain boundaries

    __shared__ float As[BK][BM];                        // [k][t]
    __shared__ float Bs[BK][BN];                        // [k][n]
    __shared__ unsigned long long red[16][BM];          // [tx][row]

    const int tid = threadIdx.x;
    const int tx = tid & 15, ty = tid >> 4;
    const float* zb = z + (size_t)b * CT + t0;

    const int la_k = tid >> 4;            // 0..15
    const int la_m = (tid & 15) * 4;      // 0..60
    const int lb_r = tid >> 2;            // 0..63
    const int lb_k = (tid & 3) * 4;

    float bestS[4];
    int bestN[4];
#pragma unroll
    for (int i = 0; i < 4; i++) { bestS[i] = __int_as_float(0x7f800000); bestN[i] = 0; }

    for (int n0 = c0; n0 < c0 + 2048; n0 += BN) {
        float acc[4][8];
#pragma unroll
        for (int i = 0; i < 4; i++)
#pragma unroll
            for (int j = 0; j < 8; j++) acc[i][j] = 0.f;

        for (int k0 = 0; k0 < E_DIM; k0 += BK) {
            float4 av  = *(const float4*)(zb + (size_t)(k0 + la_k) * T_SZ + la_m);
            float4 bv0 = *(const float4*)(g_codebook + (size_t)(n0 + lb_r) * E_DIM + k0 + lb_k);
            float4 bv1 = *(const float4*)(g_codebook + (size_t)(n0 + lb_r + 64) * E_DIM + k0 + lb_k);
            __syncthreads();
            *(float4*)&As[la_k][la_m] = av;
            Bs[lb_k + 0][lb_r] = bv0.x; Bs[lb_k + 1][lb_r] = bv0.y;
            Bs[lb_k + 2][lb_r] = bv0.z; Bs[lb_k + 3][lb_r] = bv0.w;
            Bs[lb_k + 0][lb_r + 64] = bv1.x; Bs[lb_k + 1][lb_r + 64] = bv1.y;
            Bs[lb_k + 2][lb_r + 64] = bv1.z; Bs[lb_k + 3][lb_r + 64] = bv1.w;
            __syncthreads();
#pragma unroll
            for (int k = 0; k < BK; k++) {
                float a[4], bb[8];
                *(float4*)a        = *(const float4*)&As[k][ty * 4];
                *(float4*)bb       = *(const float4*)&Bs[k][tx * 8];
                *(float4*)(bb + 4) = *(const float4*)&Bs[k][tx * 8 + 4];
#pragma unroll
                for (int i = 0; i < 4; i++)
#pragma unroll
                    for (int j = 0; j < 8; j++) acc[i][j] += a[i] * bb[j];
            }
        }
        // epilogue: score = ||cb||^2 - 2*dot ; strict < keeps smallest index on ties
#pragma unroll
        for (int j = 0; j < 8; j++) {
            int n = n0 + tx * 8 + j;
            float cn = __ldg(&g_cbnorm[n]);
#pragma unroll
            for (int i = 0; i < 4; i++) {
                float s = fmaf(-2.f, acc[i][j], cn);
                if (s < bestS[i]) { bestS[i] = s; bestN[i] = n; }
            }
        }
    }

    __syncthreads();
#pragma unroll
    for (int i = 0; i < 4; i++) {
        unsigned long long key =
            ((unsigned long long)fkey(bestS[i]) << 32) | (unsigned int)bestN[i];
        red[tx][ty * 4 + i] = key;
    }
    __syncthreads();
    if (tid < BM) {
        unsigned long long k = red[0][tid];
#pragma unroll
        for (int x = 1; x < 16; x++) {
            unsigned long long v = red[x][tid];
            if (v < k) k = v;
        }
        atomicMin(&g_best[b * T_SZ + t0 + tid], k);
    }
}

// -------- K4: gather z_q, transpose to (B,C,T), write min_idx, loss partials --------
__global__ __launch_bounds__(256) void k_gather(const float* __restrict__ z,
                                                float* __restrict__ out) {
    __shared__ int sidx[32];
    __shared__ float sred[256];
    const int blk = blockIdx.x;          // 0..255, 32 (b,t) rows each
    const int r0  = blk * 32;
    const int b   = r0 >> 10;
    const int t0  = r0 & 1023;
    const int tid = threadIdx.x;

    if (tid < 32) {
        unsigned long long key = g_best[r0 + tid];
        int idx = (int)(key & 0xffffffffull);
        sidx[tid] = idx;
        out[ZQ_ELEMS + r0 + tid] = (float)idx;   // min_idx as float
    }
    __syncthreads();

    const int t  = tid & 31;
    const int dl = tid >> 5;
    const int row = sidx[t];
    const float* cbr = g_codebook + (size_t)row * E_DIM;
    const size_t obase = (size_t)b * CT + t0 + t;
    float lacc = 0.f;
#pragma unroll 8
    for (int d = dl; d < E_DIM; d += 8) {
        float v  = cbr[d];
        float zt = z[obase + (size_t)d * T_SZ];
        float df = v - zt;
        lacc += df * df;
        out[obase + (size_t)d * T_SZ] = v;
    }
    sred[tid] = lacc;
    __syncthreads();
#pragma unroll
    for (int o = 128; o; o >>= 1) {
        if (tid < o) sred[tid] += sred[tid + o];
        __syncthreads();
    }
    if (tid == 0) g_partial[blk] = sred[0];
}

// -------- K5: finalize commit loss --------
__global__ void k_final(float* __restrict__ out) {
    __shared__ float sr[256];
    int tid = threadIdx.x;
    sr[tid] = g_partial[tid];
    __syncthreads();
#pragma unroll
    for (int o = 128; o; o >>= 1) {
        if (tid < o) sr[tid] += sr[tid + o];
        __syncthreads();
    }
    if (tid == 0)
        out[ZQ_ELEMS + ROWS] = sr[0] * 1.25f / (float)ZQ_ELEMS;
}

extern "C" void kernel_launch(void* const* d_in, const int* in_sizes, int n_in,
                              void* d_out, int out_size) {
    // identify inputs by element count (robust to scalar n_q presence)
    int i_z = -1, i_emb = -1, i_ad = -1, i_pw = -1, i_pb = -1;
    for (int i = 0; i < n_in; i++) {
        int s = in_sizes[i];
        if (s == ZQ_ELEMS) { if (i_z < 0) i_z = i; else i_emb = i; }
        else if (s == E_DIM * E_DIM) i_pw = i;
        else if (s == E_DIM)         i_pb = i;
        else if (s == B_SZ)          i_ad = i;
    }
    const float* z   = (const float*)d_in[i_z];
    const int*   ad  = (const int*)d_in[i_ad];
    const float* emb = (const float*)d_in[i_emb];
    const float* pw  = (const float*)d_in[i_pw];
    const float* pb  = (const float*)d_in[i_pb];
    float* out = (float*)d_out;

    k_ranges<<<1, 32>>>(ad);
    k_init<<<ROWS / 256, 256>>>();
    k_codebook<<<dim3(N_E / BM, E_DIM / BN), 256>>>(emb, pw, pb);
    k_cbnorm<<<N_E / 8, 256>>>();
    k_argmin<<<dim3(128, 4), 256>>>(z);
    k_gather<<<ROWS / 32, 256>>>(z, out);
    k_final<<<1, 256>>>(out);
}

// round 3
// speedup vs baseline: 4.2192x; 4.2192x over previous
#include <cuda_runtime.h>

#define N_E   8192
#define E_DIM 512
#define B_SZ  8
#define T_SZ  1024
#define ROWS  (B_SZ * T_SZ)
#define CT    (E_DIM * T_SZ)
#define ZQ_ELEMS (B_SZ * E_DIM * T_SZ)

#define BM 64
#define BN 128
#define BK 16

// -------- scratch (no allocations allowed) --------
__device__ float g_codebook[N_E * E_DIM];          // 16 MB fp32
__device__ float g_cbnorm[N_E];
__device__ unsigned short g_cb_h[N_E * E_DIM];     // bf16 hi
__device__ unsigned short g_cb_l[N_E * E_DIM];     // bf16 lo
__device__ unsigned short g_z_h[ROWS * E_DIM];     // zf row-major, bf16 hi
__device__ unsigned short g_z_l[ROWS * E_DIM];     // zf row-major, bf16 lo
__device__ unsigned long long g_best[ROWS];
__device__ float g_partial[ROWS / 32];
__device__ int g_lo[B_SZ], g_hi[B_SZ];

__device__ __forceinline__ unsigned int fkey(float f) {
    unsigned int u = __float_as_uint(f);
    return (u & 0x80000000u) ? ~u : (u | 0x80000000u);
}
__device__ __forceinline__ unsigned short f2bf(float x) {   // RN-even
    unsigned u = __float_as_uint(x);
    unsigned rb = 0x7FFFu + ((u >> 16) & 1u);
    return (unsigned short)((u + rb) >> 16);
}
__device__ __forceinline__ float bf2f(unsigned short h) {
    return __uint_as_float(((unsigned)h) << 16);
}

__device__ __forceinline__ void mma_bf16(float* c, const unsigned* a, const unsigned* b) {
    asm volatile(
        "mma.sync.aligned.m16n8k16.row.col.f32.bf16.bf16.f32 "
        "{%0,%1,%2,%3}, {%4,%5,%6,%7}, {%8,%9}, {%0,%1,%2,%3};"
        : "+f"(c[0]), "+f"(c[1]), "+f"(c[2]), "+f"(c[3])
        : "r"(a[0]), "r"(a[1]), "r"(a[2]), "r"(a[3]), "r"(b[0]), "r"(b[1]));
}

// -------- K0: parse audio_domain (int32 or int64 storage) --------
__global__ void k_ranges(const int* __restrict__ ad) {
    if (threadIdx.x == 0) {
        bool is64 = ((ad[1] | ad[3] | ad[5] | ad[7]) == 0);
        for (int b = 0; b < B_SZ; b++) {
            int dom = is64 ? ad[2 * b] : ad[b];
            int lo, hi;
            if (dom == 0)      { lo = 0;    hi = 2048; }
            else if (dom == 1) { lo = 2048; hi = 4096; }
            else if (dom == 2) { lo = 4096; hi = 8192; }
            else               { lo = 0;    hi = 8192; }
            g_lo[b] = lo; g_hi[b] = hi;
        }
    }
}

__global__ void k_init() {
    int i = blockIdx.x * blockDim.x + threadIdx.x;
    if (i < ROWS) g_best[i] = 0xFFFFFFFFFFFFFFFFull;
}

// -------- K1: codebook = emb @ proj_w^T + b (fp32 SIMT, exact) --------
__global__ __launch_bounds__(256) void k_codebook(const float* __restrict__ E,
                                                  const float* __restrict__ W,
                                                  const float* __restrict__ bias) {
    __shared__ float As[BK][BM];
    __shared__ float Bs[BK][BN];
    const int tid = threadIdx.x;
    const int tx = tid & 15, ty = tid >> 4;
    const int m0 = blockIdx.x * BM;
    const int n0 = blockIdx.y * BN;
    const int la_m = tid >> 2;
    const int la_k = (tid & 3) * 4;
    const int lb_r = tid >> 2;
    const int lb_k = (tid & 3) * 4;

    float acc[4][8];
#pragma unroll
    for (int i = 0; i < 4; i++)
#pragma unroll
        for (int j = 0; j < 8; j++) acc[i][j] = 0.f;

    for (int k0 = 0; k0 < E_DIM; k0 += BK) {
        float4 av  = *(const float4*)(E + (size_t)(m0 + la_m) * E_DIM + k0 + la_k);
        float4 bv0 = *(const float4*)(W + (size_t)(n0 + lb_r) * E_DIM + k0 + lb_k);
        float4 bv1 = *(const float4*)(W + (size_t)(n0 + lb_r + 64) * E_DIM + k0 + lb_k);
        __syncthreads();
        As[la_k + 0][la_m] = av.x; As[la_k + 1][la_m] = av.y;
        As[la_k + 2][la_m] = av.z; As[la_k + 3][la_m] = av.w;
        Bs[lb_k + 0][lb_r] = bv0.x; Bs[lb_k + 1][lb_r] = bv0.y;
        Bs[lb_k + 2][lb_r] = bv0.z; Bs[lb_k + 3][lb_r] = bv0.w;
        Bs[lb_k + 0][lb_r + 64] = bv1.x; Bs[lb_k + 1][lb_r + 64] = bv1.y;
        Bs[lb_k + 2][lb_r + 64] = bv1.z; Bs[lb_k + 3][lb_r + 64] = bv1.w;
        __syncthreads();
#pragma unroll
        for (int k = 0; k < BK; k++) {
            float a[4], bb[8];
            *(float4*)a        = *(const float4*)&As[k][ty * 4];
            *(float4*)bb       = *(const float4*)&Bs[k][tx * 8];
            *(float4*)(bb + 4) = *(const float4*)&Bs[k][tx * 8 + 4];
#pragma unroll
            for (int i = 0; i < 4; i++)
#pragma unroll
                for (int j = 0; j < 8; j++) acc[i][j] += a[i] * bb[j];
        }
    }
#pragma unroll
    for (int i = 0; i < 4; i++) {
        int row = m0 + ty * 4 + i;
        float* cp = g_codebook + (size_t)row * E_DIM + n0 + tx * 8;
        float v[8];
#pragma unroll
        for (int j = 0; j < 8; j++) v[j] = acc[i][j] + __ldg(&bias[n0 + tx * 8 + j]);
        *(float4*)cp       = *(float4*)v;
        *(float4*)(cp + 4) = *(float4*)(v + 4);
    }
}

// -------- K2: row norms --------
__global__ void k_cbnorm() {
    int row  = blockIdx.x * 8 + (threadIdx.x >> 5);
    int lane = threadIdx.x & 31;
    const float4* p = (const float4*)(g_codebook + (size_t)row * E_DIM);
    float s = 0.f;
#pragma unroll
    for (int i = lane; i < E_DIM / 4; i += 32) {
        float4 v = p[i];
        s += v.x * v.x + v.y * v.y + v.z * v.z + v.w * v.w;
    }
#pragma unroll
    for (int o = 16; o; o >>= 1) s += __shfl_down_sync(0xffffffffu, s, o);
    if (lane == 0) g_cbnorm[row] = s;
}

// -------- K2b: split codebook fp32 -> bf16 hi/lo --------
__global__ void k_split_cb() {
    int i = blockIdx.x * 256 + threadIdx.x;   // over N_E*E_DIM/4
    float4 v = ((const float4*)g_codebook)[i];
    float xs[4] = {v.x, v.y, v.z, v.w};
    ushort4 h, l;
    unsigned short* hp = &h.x; unsigned short* lp = &l.x;
#pragma unroll
    for (int j = 0; j < 4; j++) {
        unsigned short hh = f2bf(xs[j]);
        hp[j] = hh;
        lp[j] = f2bf(xs[j] - bf2f(hh));
    }
    *(ushort4*)&g_cb_h[(size_t)i * 4] = h;
    *(ushort4*)&g_cb_l[(size_t)i * 4] = l;
}

// -------- K2c: transpose z to zf row-major + split bf16 hi/lo --------
__global__ __launch_bounds__(256) void k_split_z(const float* __restrict__ z) {
    __shared__ float tile[32][33];
    const int b  = blockIdx.z;
    const int k0 = blockIdx.y * 32;
    const int t0 = blockIdx.x * 32;
    const int tx = threadIdx.x & 31;
    const int ty = threadIdx.x >> 5;   // 0..7
#pragma unroll
    for (int i = 0; i < 4; i++)
        tile[ty + 8 * i][tx] = z[(size_t)b * CT + (size_t)(k0 + ty + 8 * i) * T_SZ + t0 + tx];
    __syncthreads();
#pragma unroll
    for (int i = 0; i < 4; i++) {
        int tl = ty + 8 * i;
        float x = tile[tx][tl];
        unsigned short hh = f2bf(x);
        unsigned short ll = f2bf(x - bf2f(hh));
        size_t o = (size_t)(b * T_SZ + t0 + tl) * E_DIM + k0 + tx;
        g_z_h[o] = hh;
        g_z_l[o] = ll;
    }
}

// -------- K3: mma.sync distance GEMM + argmin --------
// grid (64, 8): blockIdx.x = 128-row tile, blockIdx.y = 1024-code chunk
#define PITCH 40   // halves per SMEM row (32 data + 8 pad) -> conflict-free frags
__global__ __launch_bounds__(256, 2) void k_argmin_wmma() {
    __shared__ unsigned short Ash[2][128 * PITCH];   // [hi/lo]
    __shared__ unsigned short Bsh[2][128 * PITCH];
    __shared__ float cn_s[1024];

    const int tid  = threadIdx.x;
    const int wid  = tid >> 5, lane = tid & 31;
    const int g    = lane >> 2, t = lane & 3;
    const int warpM = wid >> 2, warpN = wid & 3;
    const int bx = blockIdx.x;
    const int b  = bx >> 3;
    const int c0 = blockIdx.y * 1024;
    if (c0 >= g_hi[b] || c0 + 1024 <= g_lo[b]) return;

#pragma unroll
    for (int i = 0; i < 4; i++)
        cn_s[tid + 256 * i] = g_cbnorm[c0 + tid + 256 * i];

    unsigned long long best[4][2];
#pragma unroll
    for (int i = 0; i < 4; i++) { best[i][0] = ~0ull; best[i][1] = ~0ull; }

    const int lrow = tid >> 1, lpart = tid & 1;    // loader: row 0..127, 32B half
    const size_t aBase = ((size_t)bx * 128 + lrow) * E_DIM;  // halves

    for (int ng = 0; ng < 8; ng++) {
        const size_t bBase = ((size_t)(c0 + ng * 128 + lrow)) * E_DIM;
        float acc[4][4][4];
#pragma unroll
        for (int i = 0; i < 4; i++)
#pragma unroll
            for (int j = 0; j < 4; j++)
#pragma unroll
                for (int q = 0; q < 4; q++) acc[i][j][q] = 0.f;

        for (int kc = 0; kc < 16; kc++) {
            const int k0 = kc * 32;
            __syncthreads();
            {
                const uint4* pAh = (const uint4*)g_z_h  + ((aBase + k0) >> 3) + lpart * 2;
                const uint4* pAl = (const uint4*)g_z_l  + ((aBase + k0) >> 3) + lpart * 2;
                const uint4* pBh = (const uint4*)g_cb_h + ((bBase + k0) >> 3) + lpart * 2;
                const uint4* pBl = (const uint4*)g_cb_l + ((bBase + k0) >> 3) + lpart * 2;
                uint4* sAh = (uint4*)Ash[0] + lrow * 5 + lpart * 2;
                uint4* sAl = (uint4*)Ash[1] + lrow * 5 + lpart * 2;
                uint4* sBh = (uint4*)Bsh[0] + lrow * 5 + lpart * 2;
                uint4* sBl = (uint4*)Bsh[1] + lrow * 5 + lpart * 2;
                sAh[0] = pAh[0]; sAh[1] = pAh[1];
                sAl[0] = pAl[0]; sAl[1] = pAl[1];
                sBh[0] = pBh[0]; sBh[1] = pBh[1];
                sBl[0] = pBl[0]; sBl[1] = pBl[1];
            }
            __syncthreads();
#pragma unroll
            for (int ks = 0; ks < 2; ks++) {
                const int kofs = ks * 16 + 2 * t;
                unsigned bh[4][2], bl[4][2];
#pragma unroll
                for (int nt = 0; nt < 4; nt++) {
                    const int nrow = (warpN * 32 + nt * 8 + g) * PITCH + kofs;
                    bh[nt][0] = *(const unsigned*)&Bsh[0][nrow];
                    bh[nt][1] = *(const unsigned*)&Bsh[0][nrow + 8];
                    bl[nt][0] = *(const unsigned*)&Bsh[1][nrow];
                    bl[nt][1] = *(const unsigned*)&Bsh[1][nrow + 8];
                }
#pragma unroll
                for (int mt = 0; mt < 4; mt++) {
                    const int r0 = (warpM * 64 + mt * 16 + g) * PITCH + kofs;
                    unsigned ah[4], al[4];
                    ah[0] = *(const unsigned*)&Ash[0][r0];
                    ah[1] = *(const unsigned*)&Ash[0][r0 + 8 * PITCH];
                    ah[2] = *(const unsigned*)&Ash[0][r0 + 8];
                    ah[3] = *(const unsigned*)&Ash[0][r0 + 8 * PITCH + 8];
                    al[0] = *(const unsigned*)&Ash[1][r0];
                    al[1] = *(const unsigned*)&Ash[1][r0 + 8 * PITCH];
                    al[2] = *(const unsigned*)&Ash[1][r0 + 8];
                    al[3] = *(const unsigned*)&Ash[1][r0 + 8 * PITCH + 8];
#pragma unroll
                    for (int nt = 0; nt < 4; nt++) {
                        mma_bf16(acc[mt][nt], ah, bh[nt]);
                        mma_bf16(acc[mt][nt], ah, bl[nt]);
                        mma_bf16(acc[mt][nt], al, bh[nt]);
                    }
                }
            }
        }
        // epilogue: score = cn - 2*dot, fold into per-lane packed argmin
#pragma unroll
        for (int mt = 0; mt < 4; mt++)
#pragma unroll
            for (int nt = 0; nt < 4; nt++) {
                const int colL = ng * 128 + warpN * 32 + nt * 8 + 2 * t;
                const unsigned gidx = (unsigned)(c0 + colL);
                float s0 = fmaf(-2.f, acc[mt][nt][0], cn_s[colL]);
                float s1 = fmaf(-2.f, acc[mt][nt][1], cn_s[colL + 1]);
                float s2 = fmaf(-2.f, acc[mt][nt][2], cn_s[colL]);
                float s3 = fmaf(-2.f, acc[mt][nt][3], cn_s[colL + 1]);
                unsigned long long k0v = ((unsigned long long)fkey(s0) << 32) | gidx;
                unsigned long long k1v = ((unsigned long long)fkey(s1) << 32) | (gidx + 1);
                unsigned long long k2v = ((unsigned long long)fkey(s2) << 32) | gidx;
                unsigned long long k3v = ((unsigned long long)fkey(s3) << 32) | (gidx + 1);
                if (k1v < k0v) k0v = k1v;
                if (k0v < best[mt][0]) best[mt][0] = k0v;
                if (k3v < k2v) k2v = k3v;
                if (k2v < best[mt][1]) best[mt][1] = k2v;
            }
    }

    // quad reduce (lanes 4g+t share rows) then one atomic per row
#pragma unroll
    for (int mt = 0; mt < 4; mt++)
#pragma unroll
        for (int h = 0; h < 2; h++) {
            unsigned long long k = best[mt][h];
            unsigned long long o1 = __shfl_xor_sync(0xffffffffu, k, 1);
            if (o1 < k) k = o1;
            unsigned long long o2 = __shfl_xor_sync(0xffffffffu, k, 2);
            if (o2 < k) k = o2;
            if (t == 0)
                atomicMin(&g_best[bx * 128 + warpM * 64 + mt * 16 + h * 8 + g], k);
        }
}

// -------- K4: gather z_q, write min_idx, loss partials --------
__global__ __launch_bounds__(256) void k_gather(const float* __restrict__ z,
                                                float* __restrict__ out) {
    __shared__ int sidx[32];
    __shared__ float sred[256];
    const int blk = blockIdx.x;
    const int r0  = blk * 32;
    const int b   = r0 >> 10;
    const int t0  = r0 & 1023;
    const int tid = threadIdx.x;

    if (tid < 32) {
        unsigned long long key = g_best[r0 + tid];
        int idx = (int)(key & 0xffffffffull);
        sidx[tid] = idx;
        out[ZQ_ELEMS + r0 + tid] = (float)idx;
    }
    __syncthreads();

    const int t  = tid & 31;
    const int dl = tid >> 5;
    const int row = sidx[t];
    const float* cbr = g_codebook + (size_t)row * E_DIM;
    const size_t obase = (size_t)b * CT + t0 + t;
    float lacc = 0.f;
#pragma unroll 8
    for (int d = dl; d < E_DIM; d += 8) {
        float v  = cbr[d];
        float zt = z[obase + (size_t)d * T_SZ];
        float df = v - zt;
        lacc += df * df;
        out[obase + (size_t)d * T_SZ] = v;
    }
    sred[tid] = lacc;
    __syncthreads();
#pragma unroll
    for (int o = 128; o; o >>= 1) {
        if (tid < o) sred[tid] += sred[tid + o];
        __syncthreads();
    }
    if (tid == 0) g_partial[blk] = sred[0];
}

__global__ void k_final(float* __restrict__ out) {
    __shared__ float sr[256];
    int tid = threadIdx.x;
    sr[tid] = g_partial[tid];
    __syncthreads();
#pragma unroll
    for (int o = 128; o; o >>= 1) {
        if (tid < o) sr[tid] += sr[tid + o];
        __syncthreads();
    }
    if (tid == 0)
        out[ZQ_ELEMS + ROWS] = sr[0] * 1.25f / (float)ZQ_ELEMS;
}

extern "C" void kernel_launch(void* const* d_in, const int* in_sizes, int n_in,
                              void* d_out, int out_size) {
    int i_z = -1, i_emb = -1, i_ad = -1, i_pw = -1, i_pb = -1;
    for (int i = 0; i < n_in; i++) {
        int s = in_sizes[i];
        if (s == ZQ_ELEMS) { if (i_z < 0) i_z = i; else i_emb = i; }
        else if (s == E_DIM * E_DIM) i_pw = i;
        else if (s == E_DIM)         i_pb = i;
        else if (s == B_SZ)          i_ad = i;
    }
    const float* z   = (const float*)d_in[i_z];
    const int*   ad  = (const int*)d_in[i_ad];
    const float* emb = (const float*)d_in[i_emb];
    const float* pw  = (const float*)d_in[i_pw];
    const float* pb  = (const float*)d_in[i_pb];
    float* out = (float*)d_out;

    k_ranges<<<1, 32>>>(ad);
    k_init<<<ROWS / 256, 256>>>();
    k_codebook<<<dim3(N_E / BM, E_DIM / BN), 256>>>(emb, pw, pb);
    k_cbnorm<<<N_E / 8, 256>>>();
    k_split_cb<<<(N_E * E_DIM / 4) / 256, 256>>>();
    k_split_z<<<dim3(T_SZ / 32, E_DIM / 32, B_SZ), 256>>>(z);
    k_argmin_wmma<<<dim3(64, 8), 256>>>();
    k_gather<<<ROWS / 32, 256>>>(z, out);
    k_final<<<1, 256>>>(out);
}

// round 4
// speedup vs baseline: 5.9856x; 1.4187x over previous
#include <cuda_runtime.h>

#define N_E   8192
#define E_DIM 512
#define B_SZ  8
#define T_SZ  1024
#define ROWS  (B_SZ * T_SZ)
#define CT    (E_DIM * T_SZ)
#define ZQ_ELEMS (B_SZ * E_DIM * T_SZ)

#define PITCH 40                         // halves per SMEM row (32 data + 8 pad)
#define STAGE_BYTES 40960                // 4 arrays x 128 rows x PITCH x 2B
#define ARR_BYTES   10240
#define SMEM_DYN (4096 + 2 * STAGE_BYTES)

// -------- scratch (no allocations allowed) --------
__device__ float g_codebook[N_E * E_DIM];          // fp32 (gather/cbnorm)
__device__ float g_cbnorm[N_E];
__device__ unsigned short g_cb_h[N_E * E_DIM];
__device__ unsigned short g_cb_l[N_E * E_DIM];
__device__ unsigned short g_z_h[ROWS * E_DIM];
__device__ unsigned short g_z_l[ROWS * E_DIM];
__device__ unsigned short g_e_h[N_E * E_DIM];
__device__ unsigned short g_e_l[N_E * E_DIM];
__device__ unsigned short g_w_h[E_DIM * E_DIM];
__device__ unsigned short g_w_l[E_DIM * E_DIM];
__device__ unsigned long long g_best[ROWS];
__device__ float g_partial[ROWS / 32];
__device__ int g_lo[B_SZ], g_hi[B_SZ];

__device__ __forceinline__ unsigned int fkey(float f) {
    unsigned int u = __float_as_uint(f);
    return (u & 0x80000000u) ? ~u : (u | 0x80000000u);
}
__device__ __forceinline__ unsigned short f2bf(float x) {   // RN-even
    unsigned u = __float_as_uint(x);
    unsigned rb = 0x7FFFu + ((u >> 16) & 1u);
    return (unsigned short)((u + rb) >> 16);
}
__device__ __forceinline__ float bf2f(unsigned short h) {
    return __uint_as_float(((unsigned)h) << 16);
}
__device__ __forceinline__ unsigned smem_u32(const void* p) {
    unsigned a;
    asm("{ .reg .u64 t; cvta.to.shared.u64 t, %1; cvt.u32.u64 %0, t; }" : "=r"(a) : "l"(p));
    return a;
}
__device__ __forceinline__ void mma_bf16(float* c, const unsigned* a, const unsigned* b) {
    asm volatile(
        "mma.sync.aligned.m16n8k16.row.col.f32.bf16.bf16.f32 "
        "{%0,%1,%2,%3}, {%4,%5,%6,%7}, {%8,%9}, {%0,%1,%2,%3};"
        : "+f"(c[0]), "+f"(c[1]), "+f"(c[2]), "+f"(c[3])
        : "r"(a[0]), "r"(a[1]), "r"(a[2]), "r"(a[3]), "r"(b[0]), "r"(b[1]));
}
__device__ __forceinline__ void ldsm4(unsigned* r, unsigned addr) {
    asm volatile("ldmatrix.sync.aligned.m8n8.x4.shared.b16 {%0,%1,%2,%3}, [%4];"
                 : "=r"(r[0]), "=r"(r[1]), "=r"(r[2]), "=r"(r[3]) : "r"(addr));
}
__device__ __forceinline__ void cp16(unsigned dst, const void* src) {
    asm volatile("cp.async.cg.shared.global [%0], [%1], 16;" :: "r"(dst), "l"(src));
}
#define CP_COMMIT() asm volatile("cp.async.commit_group;" ::: "memory")
#define CP_WAIT0()  asm volatile("cp.async.wait_group 0;" ::: "memory")

// -------- K0: parse audio_domain (int32 or int64 storage) --------
__global__ void k_ranges(const int* __restrict__ ad) {
    if (threadIdx.x == 0) {
        bool is64 = ((ad[1] | ad[3] | ad[5] | ad[7]) == 0);
        for (int b = 0; b < B_SZ; b++) {
            int dom = is64 ? ad[2 * b] : ad[b];
            int lo, hi;
            if (dom == 0)      { lo = 0;    hi = 2048; }
            else if (dom == 1) { lo = 2048; hi = 4096; }
            else if (dom == 2) { lo = 4096; hi = 8192; }
            else               { lo = 0;    hi = 8192; }
            g_lo[b] = lo; g_hi[b] = hi;
        }
    }
}

__global__ void k_init() {
    int i = blockIdx.x * blockDim.x + threadIdx.x;
    if (i < ROWS) g_best[i] = 0xFFFFFFFFFFFFFFFFull;
}

// -------- splits: fp32 -> bf16 hi/lo --------
__global__ void k_split_emb(const float4* __restrict__ s) {
    int i = blockIdx.x * 256 + threadIdx.x;
    float4 v = s[i];
    float xs[4] = {v.x, v.y, v.z, v.w};
    ushort4 h, l;
    unsigned short* hp = &h.x; unsigned short* lp = &l.x;
#pragma unroll
    for (int j = 0; j < 4; j++) {
        unsigned short hh = f2bf(xs[j]);
        hp[j] = hh; lp[j] = f2bf(xs[j] - bf2f(hh));
    }
    *(ushort4*)&g_e_h[(size_t)i * 4] = h;
    *(ushort4*)&g_e_l[(size_t)i * 4] = l;
}
__global__ void k_split_w(const float4* __restrict__ s) {
    int i = blockIdx.x * 256 + threadIdx.x;
    float4 v = s[i];
    float xs[4] = {v.x, v.y, v.z, v.w};
    ushort4 h, l;
    unsigned short* hp = &h.x; unsigned short* lp = &l.x;
#pragma unroll
    for (int j = 0; j < 4; j++) {
        unsigned short hh = f2bf(xs[j]);
        hp[j] = hh; lp[j] = f2bf(xs[j] - bf2f(hh));
    }
    *(ushort4*)&g_w_h[(size_t)i * 4] = h;
    *(ushort4*)&g_w_l[(size_t)i * 4] = l;
}

// -------- K2c: transpose z + split --------
__global__ __launch_bounds__(256) void k_split_z(const float* __restrict__ z) {
    __shared__ float tile[32][33];
    const int b  = blockIdx.z;
    const int k0 = blockIdx.y * 32;
    const int t0 = blockIdx.x * 32;
    const int tx = threadIdx.x & 31;
    const int ty = threadIdx.x >> 5;
#pragma unroll
    for (int i = 0; i < 4; i++)
        tile[ty + 8 * i][tx] = z[(size_t)b * CT + (size_t)(k0 + ty + 8 * i) * T_SZ + t0 + tx];
    __syncthreads();
#pragma unroll
    for (int i = 0; i < 4; i++) {
        int tl = ty + 8 * i;
        float x = tile[tx][tl];
        unsigned short hh = f2bf(x);
        unsigned short ll = f2bf(x - bf2f(hh));
        size_t o = (size_t)(b * T_SZ + t0 + tl) * E_DIM + k0 + tx;
        g_z_h[o] = hh;
        g_z_l[o] = ll;
    }
}

// -------- K1: codebook = emb @ W^T + b via split-bf16 MMA; fused split epilogue --------
__global__ __launch_bounds__(256, 2) void k_codebook_mma(const float* __restrict__ bias) {
    extern __shared__ char dsm[];
    const unsigned smb = smem_u32(dsm);
    float* bias_s = (float*)dsm;

    const int tid = threadIdx.x;
    const int lane = tid & 31, wid = tid >> 5;
    const int g = lane >> 2, t = lane & 3;
    const int warpM = wid >> 2, warpN = wid & 3;
    const int bx = blockIdx.x, by = blockIdx.y;

    if (tid < 128) bias_s[tid] = bias[by * 128 + tid];

    const int lrow = tid >> 1, lpart = tid & 1;
    const size_t aG = (size_t)(bx * 128 + lrow) * E_DIM + lpart * 16;
    const size_t bG = (size_t)(by * 128 + lrow) * E_DIM + lpart * 16;
    const unsigned dOff = (unsigned)(lrow * PITCH + lpart * 16) * 2;

    const int arow = (lane < 16) ? lane : lane - 16;
    const int akadd = (lane < 16) ? 0 : 8;
    const int brow = (lane & 7) + ((lane >= 16) ? 8 : 0);
    const int bkadd = ((lane >> 3) & 1) * 8;

    float acc[4][4][4];
#pragma unroll
    for (int i = 0; i < 4; i++)
#pragma unroll
        for (int j = 0; j < 4; j++)
#pragma unroll
            for (int q = 0; q < 4; q++) acc[i][j][q] = 0.f;

    // prologue: stage 0 <- kc 0
    {
        unsigned st = smb + 4096 + dOff;
        cp16(st,                  g_e_h + aG);      cp16(st + 16,                  g_e_h + aG + 8);
        cp16(st + ARR_BYTES,      g_e_l + aG);      cp16(st + ARR_BYTES + 16,      g_e_l + aG + 8);
        cp16(st + 2 * ARR_BYTES,  g_w_h + bG);      cp16(st + 2 * ARR_BYTES + 16,  g_w_h + bG + 8);
        cp16(st + 3 * ARR_BYTES,  g_w_l + bG);      cp16(st + 3 * ARR_BYTES + 16,  g_w_l + bG + 8);
    }
    CP_COMMIT();

    for (int kc = 0; kc < 16; kc++) {
        const int s = kc & 1;
        CP_WAIT0();
        __syncthreads();
        if (kc + 1 < 16) {
            const int kk = (kc + 1) * 32;
            unsigned st = smb + 4096 + (s ^ 1) * STAGE_BYTES + dOff;
            cp16(st,                  g_e_h + aG + kk);      cp16(st + 16,                  g_e_h + aG + kk + 8);
            cp16(st + ARR_BYTES,      g_e_l + aG + kk);      cp16(st + ARR_BYTES + 16,      g_e_l + aG + kk + 8);
            cp16(st + 2 * ARR_BYTES,  g_w_h + bG + kk);      cp16(st + 2 * ARR_BYTES + 16,  g_w_h + bG + kk + 8);
            cp16(st + 3 * ARR_BYTES,  g_w_l + bG + kk);      cp16(st + 3 * ARR_BYTES + 16,  g_w_l + bG + kk + 8);
        }
        CP_COMMIT();

        const unsigned ahS = smb + 4096 + s * STAGE_BYTES;
        const unsigned alS = ahS + ARR_BYTES;
        const unsigned bhS = ahS + 2 * ARR_BYTES;
        const unsigned blS = ahS + 3 * ARR_BYTES;
#pragma unroll
        for (int ks = 0; ks < 2; ks++) {
            const int kofs = ks * 16;
            unsigned bh[2][4], bl[2][4];
#pragma unroll
            for (int p = 0; p < 2; p++) {
                unsigned ba = (unsigned)((warpN * 32 + p * 16 + brow) * PITCH + kofs + bkadd) * 2;
                ldsm4(bh[p], bhS + ba);
                ldsm4(bl[p], blS + ba);
            }
#pragma unroll
            for (int mt = 0; mt < 4; mt++) {
                unsigned aa = (unsigned)((warpM * 64 + mt * 16 + arow) * PITCH + kofs + akadd) * 2;
                unsigned ah[4], al[4];
                ldsm4(ah, ahS + aa);
                ldsm4(al, alS + aa);
#pragma unroll
                for (int nt = 0; nt < 4; nt++) {
                    const unsigned* bhp = &bh[nt >> 1][(nt & 1) * 2];
                    const unsigned* blp = &bl[nt >> 1][(nt & 1) * 2];
                    mma_bf16(acc[mt][nt], ah, bhp);
                    mma_bf16(acc[mt][nt], ah, blp);
                    mma_bf16(acc[mt][nt], al, bhp);
                }
            }
        }
    }

    // epilogue: +bias, write fp32 + hi/lo split
#pragma unroll
    for (int mt = 0; mt < 4; mt++)
#pragma unroll
        for (int nt = 0; nt < 4; nt++) {
            const int lcol = warpN * 32 + nt * 8 + 2 * t;
            const float b0 = bias_s[lcol], b1 = bias_s[lcol + 1];
            const int gc = by * 128 + lcol;
            const int r0 = bx * 128 + warpM * 64 + mt * 16 + g;
            float vv[4] = {acc[mt][nt][0] + b0, acc[mt][nt][1] + b1,
                           acc[mt][nt][2] + b0, acc[mt][nt][3] + b1};
#pragma unroll
            for (int q = 0; q < 4; q++) {
                const int r = r0 + (q >> 1) * 8;
                const size_t o = (size_t)r * E_DIM + gc + (q & 1);
                const float v = vv[q];
                g_codebook[o] = v;
                unsigned short hh = f2bf(v);
                g_cb_h[o] = hh;
                g_cb_l[o] = f2bf(v - bf2f(hh));
            }
        }
}

// -------- K2: row norms (fp32) --------
__global__ void k_cbnorm() {
    int row  = blockIdx.x * 8 + (threadIdx.x >> 5);
    int lane = threadIdx.x & 31;
    const float4* p = (const float4*)(g_codebook + (size_t)row * E_DIM);
    float s = 0.f;
#pragma unroll
    for (int i = lane; i < E_DIM / 4; i += 32) {
        float4 v = p[i];
        s += v.x * v.x + v.y * v.y + v.z * v.z + v.w * v.w;
    }
#pragma unroll
    for (int o = 16; o; o >>= 1) s += __shfl_down_sync(0xffffffffu, s, o);
    if (lane == 0) g_cbnorm[row] = s;
}

// -------- K3: distance MMA + argmin; grid (64, 8) --------
__global__ __launch_bounds__(256, 2) void k_argmin_wmma() {
    extern __shared__ char dsm[];
    const unsigned smb = smem_u32(dsm);
    float* cn_s = (float*)dsm;

    const int tid = threadIdx.x;
    const int lane = tid & 31, wid = tid >> 5;
    const int g = lane >> 2, t = lane & 3;
    const int warpM = wid >> 2, warpN = wid & 3;
    const int bx = blockIdx.x;
    const int b  = bx >> 3;
    const int c0 = blockIdx.y * 1024;
    if (c0 >= g_hi[b] || c0 + 1024 <= g_lo[b]) return;

#pragma unroll
    for (int i = 0; i < 4; i++)
        cn_s[tid + 256 * i] = g_cbnorm[c0 + tid + 256 * i];

    const int lrow = tid >> 1, lpart = tid & 1;
    const size_t aG = (size_t)(bx * 128 + lrow) * E_DIM + lpart * 16;
    const size_t bG0 = (size_t)(c0 + lrow) * E_DIM + lpart * 16;
    const unsigned dOff = (unsigned)(lrow * PITCH + lpart * 16) * 2;

    const int arow = (lane < 16) ? lane : lane - 16;
    const int akadd = (lane < 16) ? 0 : 8;
    const int brow = (lane & 7) + ((lane >= 16) ? 8 : 0);
    const int bkadd = ((lane >> 3) & 1) * 8;

    unsigned long long best[4][2];
#pragma unroll
    for (int i = 0; i < 4; i++) { best[i][0] = ~0ull; best[i][1] = ~0ull; }

    float acc[4][4][4];
#pragma unroll
    for (int i = 0; i < 4; i++)
#pragma unroll
        for (int j = 0; j < 4; j++)
#pragma unroll
            for (int q = 0; q < 4; q++) acc[i][j][q] = 0.f;

    // prologue: stage 0 <- (ng=0, kc=0)
    {
        unsigned st = smb + 4096 + dOff;
        cp16(st,                  g_z_h  + aG);      cp16(st + 16,                  g_z_h  + aG + 8);
        cp16(st + ARR_BYTES,      g_z_l  + aG);      cp16(st + ARR_BYTES + 16,      g_z_l  + aG + 8);
        cp16(st + 2 * ARR_BYTES,  g_cb_h + bG0);     cp16(st + 2 * ARR_BYTES + 16,  g_cb_h + bG0 + 8);
        cp16(st + 3 * ARR_BYTES,  g_cb_l + bG0);     cp16(st + 3 * ARR_BYTES + 16,  g_cb_l + bG0 + 8);
    }
    CP_COMMIT();

    for (int it = 0; it < 128; it++) {
        const int s = it & 1;
        CP_WAIT0();
        __syncthreads();
        if (it + 1 < 128) {
            const int ng2 = (it + 1) >> 4, kk = ((it + 1) & 15) * 32;
            const size_t aS = aG + kk;
            const size_t bS = bG0 + (size_t)(ng2 * 128) * E_DIM + kk;
            unsigned st = smb + 4096 + (s ^ 1) * STAGE_BYTES + dOff;
            cp16(st,                  g_z_h  + aS);      cp16(st + 16,                  g_z_h  + aS + 8);
            cp16(st + ARR_BYTES,      g_z_l  + aS);      cp16(st + ARR_BYTES + 16,      g_z_l  + aS + 8);
            cp16(st + 2 * ARR_BYTES,  g_cb_h + bS);      cp16(st + 2 * ARR_BYTES + 16,  g_cb_h + bS + 8);
            cp16(st + 3 * ARR_BYTES,  g_cb_l + bS);      cp16(st + 3 * ARR_BYTES + 16,  g_cb_l + bS + 8);
        }
        CP_COMMIT();

        const unsigned ahS = smb + 4096 + s * STAGE_BYTES;
        const unsigned alS = ahS + ARR_BYTES;
        const unsigned bhS = ahS + 2 * ARR_BYTES;
        const unsigned blS = ahS + 3 * ARR_BYTES;
#pragma unroll
        for (int ks = 0; ks < 2; ks++) {
            const int kofs = ks * 16;
            unsigned bh[2][4], bl[2][4];
#pragma unroll
            for (int p = 0; p < 2; p++) {
                unsigned ba = (unsigned)((warpN * 32 + p * 16 + brow) * PITCH + kofs + bkadd) * 2;
                ldsm4(bh[p], bhS + ba);
                ldsm4(bl[p], blS + ba);
            }
#pragma unroll
            for (int mt = 0; mt < 4; mt++) {
                unsigned aa = (unsigned)((warpM * 64 + mt * 16 + arow) * PITCH + kofs + akadd) * 2;
                unsigned ah[4], al[4];
                ldsm4(ah, ahS + aa);
                ldsm4(al, alS + aa);
#pragma unroll
                for (int nt = 0; nt < 4; nt++) {
                    const unsigned* bhp = &bh[nt >> 1][(nt & 1) * 2];
                    const unsigned* blp = &bl[nt >> 1][(nt & 1) * 2];
                    mma_bf16(acc[mt][nt], ah, bhp);
                    mma_bf16(acc[mt][nt], ah, blp);
                    mma_bf16(acc[mt][nt], al, bhp);
                }
            }
        }

        if ((it & 15) == 15) {
            const int ng = it >> 4;
#pragma unroll
            for (int mt = 0; mt < 4; mt++)
#pragma unroll
                for (int nt = 0; nt < 4; nt++) {
                    const int colL = ng * 128 + warpN * 32 + nt * 8 + 2 * t;
                    const unsigned gidx = (unsigned)(c0 + colL);
                    float s0 = fmaf(-2.f, acc[mt][nt][0], cn_s[colL]);
                    float s1 = fmaf(-2.f, acc[mt][nt][1], cn_s[colL + 1]);
                    float s2 = fmaf(-2.f, acc[mt][nt][2], cn_s[colL]);
                    float s3 = fmaf(-2.f, acc[mt][nt][3], cn_s[colL + 1]);
                    unsigned long long k0v = ((unsigned long long)fkey(s0) << 32) | gidx;
                    unsigned long long k1v = ((unsigned long long)fkey(s1) << 32) | (gidx + 1);
                    unsigned long long k2v = ((unsigned long long)fkey(s2) << 32) | gidx;
                    unsigned long long k3v = ((unsigned long long)fkey(s3) << 32) | (gidx + 1);
                    if (k1v < k0v) k0v = k1v;
                    if (k0v < best[mt][0]) best[mt][0] = k0v;
                    if (k3v < k2v) k2v = k3v;
                    if (k2v < best[mt][1]) best[mt][1] = k2v;
                    acc[mt][nt][0] = 0.f; acc[mt][nt][1] = 0.f;
                    acc[mt][nt][2] = 0.f; acc[mt][nt][3] = 0.f;
                }
        }
    }

#pragma unroll
    for (int mt = 0; mt < 4; mt++)
#pragma unroll
        for (int h = 0; h < 2; h++) {
            unsigned long long k = best[mt][h];
            unsigned long long o1 = __shfl_xor_sync(0xffffffffu, k, 1);
            if (o1 < k) k = o1;
            unsigned long long o2 = __shfl_xor_sync(0xffffffffu, k, 2);
            if (o2 < k) k = o2;
            if (t == 0)
                atomicMin(&g_best[bx * 128 + warpM * 64 + mt * 16 + h * 8 + g], k);
        }
}

// -------- K4: gather z_q, write min_idx, loss partials --------
__global__ __launch_bounds__(256) void k_gather(const float* __restrict__ z,
                                                float* __restrict__ out) {
    __shared__ int sidx[32];
    __shared__ float sred[256];
    const int blk = blockIdx.x;
    const int r0  = blk * 32;
    const int b   = r0 >> 10;
    const int t0  = r0 & 1023;
    const int tid = threadIdx.x;

    if (tid < 32) {
        unsigned long long key = g_best[r0 + tid];
        int idx = (int)(key & 0xffffffffull);
        sidx[tid] = idx;
        out[ZQ_ELEMS + r0 + tid] = (float)idx;
    }
    __syncthreads();

    const int t  = tid & 31;
    const int dl = tid >> 5;
    const int row = sidx[t];
    const float* cbr = g_codebook + (size_t)row * E_DIM;
    const size_t obase = (size_t)b * CT + t0 + t;
    float lacc = 0.f;
#pragma unroll 8
    for (int d = dl; d < E_DIM; d += 8) {
        float v  = cbr[d];
        float zt = z[obase + (size_t)d * T_SZ];
        float df = v - zt;
        lacc += df * df;
        out[obase + (size_t)d * T_SZ] = v;
    }
    sred[tid] = lacc;
    __syncthreads();
#pragma unroll
    for (int o = 128; o; o >>= 1) {
        if (tid < o) sred[tid] += sred[tid + o];
        __syncthreads();
    }
    if (tid == 0) g_partial[blk] = sred[0];
}

__global__ void k_final(float* __restrict__ out) {
    __shared__ float sr[256];
    int tid = threadIdx.x;
    sr[tid] = g_partial[tid];
    __syncthreads();
#pragma unroll
    for (int o = 128; o; o >>= 1) {
        if (tid < o) sr[tid] += sr[tid + o];
        __syncthreads();
    }
    if (tid == 0)
        out[ZQ_ELEMS + ROWS] = sr[0] * 1.25f / (float)ZQ_ELEMS;
}

extern "C" void kernel_launch(void* const* d_in, const int* in_sizes, int n_in,
                              void* d_out, int out_size) {
    int i_z = -1, i_emb = -1, i_ad = -1, i_pw = -1, i_pb = -1;
    for (int i = 0; i < n_in; i++) {
        int s = in_sizes[i];
        if (s == ZQ_ELEMS) { if (i_z < 0) i_z = i; else i_emb = i; }
        else if (s == E_DIM * E_DIM) i_pw = i;
        else if (s == E_DIM)         i_pb = i;
        else if (s == B_SZ)          i_ad = i;
    }
    const float* z   = (const float*)d_in[i_z];
    const int*   ad  = (const int*)d_in[i_ad];
    const float* emb = (const float*)d_in[i_emb];
    const float* pw  = (const float*)d_in[i_pw];
    const float* pb  = (const float*)d_in[i_pb];
    float* out = (float*)d_out;

    cudaFuncSetAttribute(k_codebook_mma, cudaFuncAttributeMaxDynamicSharedMemorySize, SMEM_DYN);
    cudaFuncSetAttribute(k_argmin_wmma,  cudaFuncAttributeMaxDynamicSharedMemorySize, SMEM_DYN);

    k_ranges<<<1, 32>>>(ad);
    k_init<<<ROWS / 256, 256>>>();
    k_split_emb<<<(N_E * E_DIM / 4) / 256, 256>>>((const float4*)emb);
    k_split_w<<<(E_DIM * E_DIM / 4) / 256, 256>>>((const float4*)pw);
    k_split_z<<<dim3(T_SZ / 32, E_DIM / 32, B_SZ), 256>>>(z);
    k_codebook_mma<<<dim3(N_E / 128, E_DIM / 128), 256, SMEM_DYN>>>(pb);
    k_cbnorm<<<N_E / 8, 256>>>();
    k_argmin_wmma<<<dim3(64, 8), 256, SMEM_DYN>>>();
    k_gather<<<ROWS / 32, 256>>>(z, out);
    k_final<<<1, 256>>>(out);
}

// round 5
// speedup vs baseline: 7.3640x; 1.2303x over previous
#include <cuda_runtime.h>

#define N_E   8192
#define E_DIM 512
#define B_SZ  8
#define T_SZ  1024
#define ROWS  (B_SZ * T_SZ)
#define CT    (E_DIM * T_SZ)
#define ZQ_ELEMS (B_SZ * E_DIM * T_SZ)

#define PITCH 40                         // halves per SMEM row (32 data + 8 pad)
#define ARR_BYTES   10240                // 128 rows x PITCH x 2B
#define MARGIN 1.0f

// codebook kernel smem: 4KB + 2 stages x 4 arrays
#define CB_STAGE (4 * ARR_BYTES)
#define SMEM_CB  (4096 + 2 * CB_STAGE)
// argmin kernel smem: 2 stages x 2 arrays (hi only)
#define AG_STAGE (2 * ARR_BYTES)
#define SMEM_AG  (2 * AG_STAGE)

// -------- scratch (no allocations allowed) --------
__device__ float g_codebook[N_E * E_DIM];
__device__ float g_cbnorm[N_E];
__device__ unsigned short g_cb_h[N_E * E_DIM];
__device__ unsigned short g_z_h[ROWS * E_DIM];
__device__ unsigned short g_e_h[N_E * E_DIM];
__device__ unsigned short g_e_l[N_E * E_DIM];
__device__ unsigned short g_w_h[E_DIM * E_DIM];
__device__ unsigned short g_w_l[E_DIM * E_DIM];
__device__ float g_scores[(size_t)ROWS * N_E];     // raw bf16-pass dots (256MB)
__device__ unsigned long long g_best[ROWS];
__device__ float g_partial[ROWS / 32];
__device__ int g_lo[B_SZ], g_hi[B_SZ];

__device__ __forceinline__ unsigned int fkey(float f) {
    unsigned int u = __float_as_uint(f);
    return (u & 0x80000000u) ? ~u : (u | 0x80000000u);
}
__device__ __forceinline__ unsigned short f2bf(float x) {   // RN-even
    unsigned u = __float_as_uint(x);
    unsigned rb = 0x7FFFu + ((u >> 16) & 1u);
    return (unsigned short)((u + rb) >> 16);
}
__device__ __forceinline__ float bf2f(unsigned short h) {
    return __uint_as_float(((unsigned)h) << 16);
}
__device__ __forceinline__ unsigned smem_u32(const void* p) {
    unsigned a;
    asm("{ .reg .u64 t; cvta.to.shared.u64 t, %1; cvt.u32.u64 %0, t; }" : "=r"(a) : "l"(p));
    return a;
}
__device__ __forceinline__ void mma_bf16(float* c, const unsigned* a, const unsigned* b) {
    asm volatile(
        "mma.sync.aligned.m16n8k16.row.col.f32.bf16.bf16.f32 "
        "{%0,%1,%2,%3}, {%4,%5,%6,%7}, {%8,%9}, {%0,%1,%2,%3};"
        : "+f"(c[0]), "+f"(c[1]), "+f"(c[2]), "+f"(c[3])
        : "r"(a[0]), "r"(a[1]), "r"(a[2]), "r"(a[3]), "r"(b[0]), "r"(b[1]));
}
__device__ __forceinline__ void ldsm4(unsigned* r, unsigned addr) {
    asm volatile("ldmatrix.sync.aligned.m8n8.x4.shared.b16 {%0,%1,%2,%3}, [%4];"
                 : "=r"(r[0]), "=r"(r[1]), "=r"(r[2]), "=r"(r[3]) : "r"(addr));
}
__device__ __forceinline__ void cp16(unsigned dst, const void* src) {
    asm volatile("cp.async.cg.shared.global [%0], [%1], 16;" :: "r"(dst), "l"(src));
}
#define CP_COMMIT() asm volatile("cp.async.commit_group;" ::: "memory")
#define CP_WAIT0()  asm volatile("cp.async.wait_group 0;" ::: "memory")

// ======== L1: setup — domain ranges + zero cbnorm ========
__global__ void k_setup(const int* __restrict__ ad) {
    int i = blockIdx.x * 256 + threadIdx.x;
    if (i < N_E) g_cbnorm[i] = 0.f;
    if (i == 0) {
        bool is64 = ((ad[1] | ad[3] | ad[5] | ad[7]) == 0);
        for (int b = 0; b < B_SZ; b++) {
            int dom = is64 ? ad[2 * b] : ad[b];
            int lo, hi;
            if (dom == 0)      { lo = 0;    hi = 2048; }
            else if (dom == 1) { lo = 2048; hi = 4096; }
            else if (dom == 2) { lo = 4096; hi = 8192; }
            else               { lo = 0;    hi = 8192; }
            g_lo[b] = lo; g_hi[b] = hi;
        }
    }
}

// ======== L2: fused splits (emb hi/lo | W hi/lo | z transpose hi) ========
#define EBLK (N_E * E_DIM / 4 / 256)     // 4096
#define WBLK (E_DIM * E_DIM / 4 / 256)   // 256
#define ZBLK 4096                        // 32 x 16 x 8
__global__ __launch_bounds__(256) void k_split_all(const float* __restrict__ emb,
                                                   const float* __restrict__ pw,
                                                   const float* __restrict__ z) {
    const int blk = blockIdx.x;
    const int tid = threadIdx.x;
    if (blk < EBLK) {
        int i = blk * 256 + tid;
        float4 v = ((const float4*)emb)[i];
        float xs[4] = {v.x, v.y, v.z, v.w};
        ushort4 h, l;
        unsigned short* hp = &h.x; unsigned short* lp = &l.x;
#pragma unroll
        for (int j = 0; j < 4; j++) {
            unsigned short hh = f2bf(xs[j]);
            hp[j] = hh; lp[j] = f2bf(xs[j] - bf2f(hh));
        }
        *(ushort4*)&g_e_h[(size_t)i * 4] = h;
        *(ushort4*)&g_e_l[(size_t)i * 4] = l;
    } else if (blk < EBLK + WBLK) {
        int i = (blk - EBLK) * 256 + tid;
        float4 v = ((const float4*)pw)[i];
        float xs[4] = {v.x, v.y, v.z, v.w};
        ushort4 h, l;
        unsigned short* hp = &h.x; unsigned short* lp = &l.x;
#pragma unroll
        for (int j = 0; j < 4; j++) {
            unsigned short hh = f2bf(xs[j]);
            hp[j] = hh; lp[j] = f2bf(xs[j] - bf2f(hh));
        }
        *(ushort4*)&g_w_h[(size_t)i * 4] = h;
        *(ushort4*)&g_w_l[(size_t)i * 4] = l;
    } else {
        __shared__ float tile[32][33];
        const int zi = blk - (EBLK + WBLK);
        const int t0 = (zi & 31) * 32;
        const int k0 = ((zi >> 5) & 15) * 32;
        const int b  = zi >> 9;
        const int tx = tid & 31;
        const int ty = tid >> 5;
#pragma unroll
        for (int i = 0; i < 4; i++)
            tile[ty + 8 * i][tx] = z[(size_t)b * CT + (size_t)(k0 + ty + 8 * i) * T_SZ + t0 + tx];
        __syncthreads();
#pragma unroll
        for (int i = 0; i < 4; i++) {
            int tl = ty + 8 * i;
            g_z_h[(size_t)(b * T_SZ + t0 + tl) * E_DIM + k0 + tx] = f2bf(tile[tx][tl]);
        }
    }
}

// ======== L3: codebook = emb @ W^T + b (3-term split MMA) + fused cbnorm ========
__global__ __launch_bounds__(256, 2) void k_codebook_mma(const float* __restrict__ bias) {
    extern __shared__ char dsm[];
    const unsigned smb = smem_u32(dsm);
    float* bias_s = (float*)dsm;

    const int tid = threadIdx.x;
    const int lane = tid & 31, wid = tid >> 5;
    const int g = lane >> 2, t = lane & 3;
    const int warpM = wid >> 2, warpN = wid & 3;
    const int bx = blockIdx.x, by = blockIdx.y;

    if (tid < 128) bias_s[tid] = bias[by * 128 + tid];

    const int lrow = tid >> 1, lpart = tid & 1;
    const size_t aG = (size_t)(bx * 128 + lrow) * E_DIM + lpart * 16;
    const size_t bG = (size_t)(by * 128 + lrow) * E_DIM + lpart * 16;
    const unsigned dOff = (unsigned)(lrow * PITCH + lpart * 16) * 2;

    const int arow = (lane < 16) ? lane : lane - 16;
    const int akadd = (lane < 16) ? 0 : 8;
    const int brow = (lane & 7) + ((lane >= 16) ? 8 : 0);
    const int bkadd = ((lane >> 3) & 1) * 8;

    float acc[4][4][4];
#pragma unroll
    for (int i = 0; i < 4; i++)
#pragma unroll
        for (int j = 0; j < 4; j++)
#pragma unroll
            for (int q = 0; q < 4; q++) acc[i][j][q] = 0.f;

    {
        unsigned st = smb + 4096 + dOff;
        cp16(st,                  g_e_h + aG);      cp16(st + 16,                  g_e_h + aG + 8);
        cp16(st + ARR_BYTES,      g_e_l + aG);      cp16(st + ARR_BYTES + 16,      g_e_l + aG + 8);
        cp16(st + 2 * ARR_BYTES,  g_w_h + bG);      cp16(st + 2 * ARR_BYTES + 16,  g_w_h + bG + 8);
        cp16(st + 3 * ARR_BYTES,  g_w_l + bG);      cp16(st + 3 * ARR_BYTES + 16,  g_w_l + bG + 8);
    }
    CP_COMMIT();

    for (int kc = 0; kc < 16; kc++) {
        const int s = kc & 1;
        CP_WAIT0();
        __syncthreads();
        if (kc + 1 < 16) {
            const int kk = (kc + 1) * 32;
            unsigned st = smb + 4096 + (s ^ 1) * CB_STAGE + dOff;
            cp16(st,                  g_e_h + aG + kk);      cp16(st + 16,                  g_e_h + aG + kk + 8);
            cp16(st + ARR_BYTES,      g_e_l + aG + kk);      cp16(st + ARR_BYTES + 16,      g_e_l + aG + kk + 8);
            cp16(st + 2 * ARR_BYTES,  g_w_h + bG + kk);      cp16(st + 2 * ARR_BYTES + 16,  g_w_h + bG + kk + 8);
            cp16(st + 3 * ARR_BYTES,  g_w_l + bG + kk);      cp16(st + 3 * ARR_BYTES + 16,  g_w_l + bG + kk + 8);
        }
        CP_COMMIT();

        const unsigned ahS = smb + 4096 + s * CB_STAGE;
        const unsigned alS = ahS + ARR_BYTES;
        const unsigned bhS = ahS + 2 * ARR_BYTES;
        const unsigned blS = ahS + 3 * ARR_BYTES;
#pragma unroll
        for (int ks = 0; ks < 2; ks++) {
            const int kofs = ks * 16;
            unsigned bh[2][4], bl[2][4];
#pragma unroll
            for (int p = 0; p < 2; p++) {
                unsigned ba = (unsigned)((warpN * 32 + p * 16 + brow) * PITCH + kofs + bkadd) * 2;
                ldsm4(bh[p], bhS + ba);
                ldsm4(bl[p], blS + ba);
            }
#pragma unroll
            for (int mt = 0; mt < 4; mt++) {
                unsigned aa = (unsigned)((warpM * 64 + mt * 16 + arow) * PITCH + kofs + akadd) * 2;
                unsigned ah[4], al[4];
                ldsm4(ah, ahS + aa);
                ldsm4(al, alS + aa);
#pragma unroll
                for (int nt = 0; nt < 4; nt++) {
                    const unsigned* bhp = &bh[nt >> 1][(nt & 1) * 2];
                    const unsigned* blp = &bl[nt >> 1][(nt & 1) * 2];
                    mma_bf16(acc[mt][nt], ah, bhp);
                    mma_bf16(acc[mt][nt], ah, blp);
                    mma_bf16(acc[mt][nt], al, bhp);
                }
            }
        }
    }

    // epilogue: +bias; write fp32 cb + bf16 hi; fused row-norm partials
#pragma unroll
    for (int mt = 0; mt < 4; mt++) {
        float nrm0 = 0.f, nrm1 = 0.f;   // rows r0 and r0+8
#pragma unroll
        for (int nt = 0; nt < 4; nt++) {
            const int lcol = warpN * 32 + nt * 8 + 2 * t;
            const float b0 = bias_s[lcol], b1 = bias_s[lcol + 1];
            const int gc = by * 128 + lcol;
            const int r0 = bx * 128 + warpM * 64 + mt * 16 + g;
            float v0 = acc[mt][nt][0] + b0, v1 = acc[mt][nt][1] + b1;
            float v2 = acc[mt][nt][2] + b0, v3 = acc[mt][nt][3] + b1;
            size_t o0 = (size_t)r0 * E_DIM + gc;
            size_t o1 = (size_t)(r0 + 8) * E_DIM + gc;
            g_codebook[o0] = v0;     g_codebook[o0 + 1] = v1;
            g_codebook[o1] = v2;     g_codebook[o1 + 1] = v3;
            g_cb_h[o0] = f2bf(v0);   g_cb_h[o0 + 1] = f2bf(v1);
            g_cb_h[o1] = f2bf(v2);   g_cb_h[o1 + 1] = f2bf(v3);
            nrm0 += v0 * v0 + v1 * v1;
            nrm1 += v2 * v2 + v3 * v3;
        }
        nrm0 += __shfl_xor_sync(0xffffffffu, nrm0, 1);
        nrm0 += __shfl_xor_sync(0xffffffffu, nrm0, 2);
        nrm1 += __shfl_xor_sync(0xffffffffu, nrm1, 1);
        nrm1 += __shfl_xor_sync(0xffffffffu, nrm1, 2);
        if (t == 0) {
            const int r0 = bx * 128 + warpM * 64 + mt * 16 + g;
            atomicAdd(&g_cbnorm[r0], nrm0);
            atomicAdd(&g_cbnorm[r0 + 8], nrm1);
        }
    }
}

// ======== L4: 1-term bf16 distance MMA; writes raw dots ========
__global__ __launch_bounds__(256, 2) void k_argmin_1t() {
    extern __shared__ char dsm[];
    const unsigned smb = smem_u32(dsm);

    const int tid = threadIdx.x;
    const int lane = tid & 31, wid = tid >> 5;
    const int g = lane >> 2, t = lane & 3;
    const int warpM = wid >> 2, warpN = wid & 3;
    const int bx = blockIdx.x;
    const int b  = bx >> 3;
    const int c0 = blockIdx.y * 1024;
    if (c0 >= g_hi[b] || c0 + 1024 <= g_lo[b]) return;

    const int lrow = tid >> 1, lpart = tid & 1;
    const size_t aG  = (size_t)(bx * 128 + lrow) * E_DIM + lpart * 16;
    const size_t bG0 = (size_t)(c0 + lrow) * E_DIM + lpart * 16;
    const unsigned dOff = (unsigned)(lrow * PITCH + lpart * 16) * 2;

    const int arow = (lane < 16) ? lane : lane - 16;
    const int akadd = (lane < 16) ? 0 : 8;
    const int brow = (lane & 7) + ((lane >= 16) ? 8 : 0);
    const int bkadd = ((lane >> 3) & 1) * 8;

    float acc[4][4][4];
#pragma unroll
    for (int i = 0; i < 4; i++)
#pragma unroll
        for (int j = 0; j < 4; j++)
#pragma unroll
            for (int q = 0; q < 4; q++) acc[i][j][q] = 0.f;

    {
        unsigned st = smb + dOff;
        cp16(st,             g_z_h  + aG);   cp16(st + 16,             g_z_h  + aG + 8);
        cp16(st + ARR_BYTES, g_cb_h + bG0);  cp16(st + ARR_BYTES + 16, g_cb_h + bG0 + 8);
    }
    CP_COMMIT();

    for (int it = 0; it < 128; it++) {
        const int s = it & 1;
        CP_WAIT0();
        __syncthreads();
        if (it + 1 < 128) {
            const int ng2 = (it + 1) >> 4, kk = ((it + 1) & 15) * 32;
            const size_t aS = aG + kk;
            const size_t bS = bG0 + (size_t)(ng2 * 128) * E_DIM + kk;
            unsigned st = smb + (s ^ 1) * AG_STAGE + dOff;
            cp16(st,             g_z_h  + aS);   cp16(st + 16,             g_z_h  + aS + 8);
            cp16(st + ARR_BYTES, g_cb_h + bS);   cp16(st + ARR_BYTES + 16, g_cb_h + bS + 8);
        }
        CP_COMMIT();

        const unsigned ahS = smb + s * AG_STAGE;
        const unsigned bhS = ahS + ARR_BYTES;
#pragma unroll
        for (int ks = 0; ks < 2; ks++) {
            const int kofs = ks * 16;
            unsigned bh[2][4];
#pragma unroll
            for (int p = 0; p < 2; p++) {
                unsigned ba = (unsigned)((warpN * 32 + p * 16 + brow) * PITCH + kofs + bkadd) * 2;
                ldsm4(bh[p], bhS + ba);
            }
#pragma unroll
            for (int mt = 0; mt < 4; mt++) {
                unsigned aa = (unsigned)((warpM * 64 + mt * 16 + arow) * PITCH + kofs + akadd) * 2;
                unsigned ah[4];
                ldsm4(ah, ahS + aa);
#pragma unroll
                for (int nt = 0; nt < 4; nt++)
                    mma_bf16(acc[mt][nt], ah, &bh[nt >> 1][(nt & 1) * 2]);
            }
        }

        if ((it & 15) == 15) {
            const int ng = it >> 4;
#pragma unroll
            for (int mt = 0; mt < 4; mt++) {
                const int r0 = bx * 128 + warpM * 64 + mt * 16 + g;
#pragma unroll
                for (int nt = 0; nt < 4; nt++) {
                    const int col = c0 + ng * 128 + warpN * 32 + nt * 8 + 2 * t;
                    float2 v01 = {acc[mt][nt][0], acc[mt][nt][1]};
                    float2 v23 = {acc[mt][nt][2], acc[mt][nt][3]};
                    *(float2*)&g_scores[(size_t)r0 * N_E + col]       = v01;
                    *(float2*)&g_scores[(size_t)(r0 + 8) * N_E + col] = v23;
                    acc[mt][nt][0] = 0.f; acc[mt][nt][1] = 0.f;
                    acc[mt][nt][2] = 0.f; acc[mt][nt][3] = 0.f;
                }
            }
        }
    }
}

// ======== L5: scan bf16 scores, collect candidates, exact fp32 rescore ========
__global__ __launch_bounds__(256) void k_scan(const float* __restrict__ z) {
    __shared__ float smin_s[256];
    __shared__ int   scnt;
    __shared__ int   cand[1024];
    __shared__ unsigned long long wbest[8];

    const int row = blockIdx.x;
    const int tid = threadIdx.x;
    const int lane = tid & 31, wid = tid >> 5;
    const int b = row >> 10;
    const int lo = g_lo[b], hi = g_hi[b];
    const float* srow = g_scores + (size_t)row * N_E;

    // pass 1: min of bf16 scores
    float m = __int_as_float(0x7f800000);
    for (int j = lo + tid; j < hi; j += 256) {
        float s = fmaf(-2.f, srow[j], g_cbnorm[j]);
        if (s < m) m = s;
    }
    smin_s[tid] = m;
    __syncthreads();
#pragma unroll
    for (int o = 128; o; o >>= 1) {
        if (tid < o && smin_s[tid + o] < smin_s[tid]) smin_s[tid] = smin_s[tid + o];
        __syncthreads();
    }
    const float thresh = smin_s[0] + MARGIN;
    if (tid == 0) scnt = 0;
    __syncthreads();

    // pass 2: collect candidates (L1-hot reread)
    for (int j = lo + tid; j < hi; j += 256) {
        float s = fmaf(-2.f, srow[j], g_cbnorm[j]);
        if (s <= thresh) {
            int pos = atomicAdd(&scnt, 1);
            if (pos < 1024) cand[pos] = j;
        }
    }
    __syncthreads();
    int nc = scnt < 1024 ? scnt : 1024;

    // rescore candidates exactly in fp32; warp per candidate
    unsigned long long best = ~0ull;
    const size_t zbase = (size_t)b * CT + (row & 1023);
    for (int ci = wid; ci < nc; ci += 8) {
        const int j = cand[ci];
        const float* cbr = g_codebook + (size_t)j * E_DIM;
        float dot = 0.f;
#pragma unroll
        for (int d = lane; d < E_DIM; d += 32)
            dot = fmaf(z[zbase + (size_t)d * T_SZ], cbr[d], dot);
#pragma unroll
        for (int o = 16; o; o >>= 1) dot += __shfl_xor_sync(0xffffffffu, dot, o);
        float s = fmaf(-2.f, dot, g_cbnorm[j]);
        unsigned long long key = ((unsigned long long)fkey(s) << 32) | (unsigned)j;
        if (key < best) best = key;
    }
    if (lane == 0) wbest[wid] = best;
    __syncthreads();
    if (tid == 0) {
        unsigned long long k = wbest[0];
#pragma unroll
        for (int w = 1; w < 8; w++)
            if (wbest[w] < k) k = wbest[w];
        g_best[row] = k;
    }
}

// ======== L6: gather z_q, write min_idx, loss partials ========
__global__ __launch_bounds__(256) void k_gather(const float* __restrict__ z,
                                                float* __restrict__ out) {
    __shared__ int sidx[32];
    __shared__ float sred[256];
    const int blk = blockIdx.x;
    const int r0  = blk * 32;
    const int b   = r0 >> 10;
    const int t0  = r0 & 1023;
    const int tid = threadIdx.x;

    if (tid < 32) {
        unsigned long long key = g_best[r0 + tid];
        int idx = (int)(key & 0xffffffffull);
        sidx[tid] = idx;
        out[ZQ_ELEMS + r0 + tid] = (float)idx;
    }
    __syncthreads();

    const int t  = tid & 31;
    const int dl = tid >> 5;
    const int row = sidx[t];
    const float* cbr = g_codebook + (size_t)row * E_DIM;
    const size_t obase = (size_t)b * CT + t0 + t;
    float lacc = 0.f;
#pragma unroll 8
    for (int d = dl; d < E_DIM; d += 8) {
        float v  = cbr[d];
        float zt = z[obase + (size_t)d * T_SZ];
        float df = v - zt;
        lacc += df * df;
        out[obase + (size_t)d * T_SZ] = v;
    }
    sred[tid] = lacc;
    __syncthreads();
#pragma unroll
    for (int o = 128; o; o >>= 1) {
        if (tid < o) sred[tid] += sred[tid + o];
        __syncthreads();
    }
    if (tid == 0) g_partial[blk] = sred[0];
}

// ======== L7: finalize loss ========
__global__ void k_final(float* __restrict__ out) {
    __shared__ float sr[256];
    int tid = threadIdx.x;
    sr[tid] = g_partial[tid];
    __syncthreads();
#pragma unroll
    for (int o = 128; o; o >>= 1) {
        if (tid < o) sr[tid] += sr[tid + o];
        __syncthreads();
    }
    if (tid == 0)
        out[ZQ_ELEMS + ROWS] = sr[0] * 1.25f / (float)ZQ_ELEMS;
}

extern "C" void kernel_launch(void* const* d_in, const int* in_sizes, int n_in,
                              void* d_out, int out_size) {
    int i_z = -1, i_emb = -1, i_ad = -1, i_pw = -1, i_pb = -1;
    for (int i = 0; i < n_in; i++) {
        int s = in_sizes[i];
        if (s == ZQ_ELEMS) { if (i_z < 0) i_z = i; else i_emb = i; }
        else if (s == E_DIM * E_DIM) i_pw = i;
        else if (s == E_DIM)         i_pb = i;
        else if (s == B_SZ)          i_ad = i;
    }
    const float* z   = (const float*)d_in[i_z];
    const int*   ad  = (const int*)d_in[i_ad];
    const float* emb = (const float*)d_in[i_emb];
    const float* pw  = (const float*)d_in[i_pw];
    const float* pb  = (const float*)d_in[i_pb];
    float* out = (float*)d_out;

    cudaFuncSetAttribute(k_codebook_mma, cudaFuncAttributeMaxDynamicSharedMemorySize, SMEM_CB);
    cudaFuncSetAttribute(k_argmin_1t,    cudaFuncAttributeMaxDynamicSharedMemorySize, SMEM_AG);

    k_setup<<<N_E / 256, 256>>>(ad);                                        // 1
    k_split_all<<<EBLK + WBLK + ZBLK, 256>>>(emb, pw, z);                   // 2
    k_codebook_mma<<<dim3(N_E / 128, E_DIM / 128), 256, SMEM_CB>>>(pb);     // 3
    k_argmin_1t<<<dim3(64, 8), 256, SMEM_AG>>>();                           // 4 (profiled)
    k_scan<<<ROWS, 256>>>(z);                                               // 5
    k_gather<<<ROWS / 32, 256>>>(z, out);                                   // 6
    k_final<<<1, 256>>>(out);                                               // 7
}